// round 16
// baseline (speedup 1.0000x reference)
#include <cuda_runtime.h>

// Stacked LSTM: B=64, T=512, D=256, H=512, 3 layers. fp32.
// R16 WAVEFRONT: all 3 layers advance concurrently, ONE grid barrier per
// global step s (514 steps vs 1536): layer0 computes t=s, layer1 t=s-1,
// layer2 t=s-2. Block bc owns units [4bc,4bc+4) of ALL layers (3x16 z-cols).
// All weights (2816 K-rows x 16 cols = 180KB) resident in smem; A panels
// (x0 / h ping-pong buffers) stream from L2 directly to registers (no A
// staging, no seq buffers: layer l+1's x-input IS h_l from the previous
// step's ping-pong slot). Warp = (ks<8, rh<2): 32 rows x 16 cols x K/8;
// thread 2 rows x 8 cols, packed f32x2 FFMA, w broadcast from smem.

#define Bsz 64
#define Tsz 512
#define Dsz 256
#define Hsz 512
#define Gsz 2048
#define NBLK 128
#define NTHR 512
#define NSTEP 514

typedef unsigned long long u64;

// smem floats: w_s [2816][16] = 45056 | zred [8][64][18] = 9216 | bias [3][16] = 48
#define SM_WS   0
#define SM_ZR   45056
#define SM_BIAS (45056 + 9216)
#define SMEM_FLOATS (SM_BIAS + 48)
#define SMEM_BYTES (SMEM_FLOATS * 4)   // 217,280 B

__device__ float g_H[3][2][Bsz * Hsz];   // per-layer h ping-pong
__device__ unsigned g_count = 0;
__device__ unsigned g_gen = 0;

// ---- split-phase grid barrier (single counter; snapshot-based) ----
__device__ __forceinline__ void bar_arrive(unsigned* s_my) {
    __syncthreads();
    if (threadIdx.x == 0) {
        unsigned my;
        asm volatile("ld.relaxed.gpu.u32 %0, [%1];" : "=r"(my) : "l"(&g_gen));
        *s_my = my;
        __threadfence();
        unsigned old = atomicAdd(&g_count, 1u);
        if (old == NBLK - 1) {
            g_count = 0;
            __threadfence();
            asm volatile("st.release.gpu.u32 [%0], %1;" :: "l"(&g_gen), "r"(my + 1u));
        }
    }
}
__device__ __forceinline__ void bar_wait(unsigned* s_my) {
    if (threadIdx.x == 0) {
        unsigned my = *s_my, g;
        do {
            asm volatile("ld.acquire.gpu.u32 %0, [%1];" : "=r"(g) : "l"(&g_gen));
        } while (g == my);
    }
    __syncthreads();
}

__device__ __forceinline__ float fsig(float x) {
    return __fdividef(1.0f, 1.0f + __expf(-x));
}
__device__ __forceinline__ float ftanh(float x) {
    float e = __expf(2.0f * x);
    return 1.0f - __fdividef(2.0f, e + 1.0f);
}
__device__ __forceinline__ void fma2(u64& d, u64 a, u64 b) {
    asm("fma.rn.f32x2 %0, %1, %2, %0;" : "+l"(d) : "l"(a), "l"(b));
}
__device__ __forceinline__ u64 rep2(float x) {
    u64 r;
    asm("mov.b64 %0, {%1, %1};" : "=l"(r) : "f"(x));
    return r;
}

extern "C" __global__ void __launch_bounds__(NTHR, 1)
lstm_kernel(const float* __restrict__ x0,
            const float* __restrict__ W0, const float* __restrict__ U0, const float* __restrict__ b0,
            const float* __restrict__ W1, const float* __restrict__ U1, const float* __restrict__ b1,
            const float* __restrict__ W2, const float* __restrict__ U2, const float* __restrict__ b2,
            float* __restrict__ out)
{
    extern __shared__ float smem[];
    float* w_s    = smem + SM_WS;    // [2816][16]
    float* zred   = smem + SM_ZR;    // [8][64][18]
    float* bias_s = smem + SM_BIAS;  // [3][16]
    __shared__ unsigned s_my;

    const int tid  = threadIdx.x;
    const int bc   = blockIdx.x;
    const int j0   = bc * 4;
    const int wid  = tid >> 5;
    const int ks   = wid & 7;         // k-split group
    const int rh   = wid >> 3;        // row half
    const int lane = tid & 31;
    const int rg   = lane & 15;
    const int cgp  = lane >> 4;       // col half (8 cols)
    const int r0   = rh * 32 + rg;    // thread rows r0, r1
    const int r1   = r0 + 16;
    const int gb   = (tid & 255) >> 2;
    const int gj   = tid & 3;

    // ---- load ALL weights into smem once ----
    // w_s row map: [0,256)=W0 | [256,768)=U0 | [768,1280)=W1 | [1280,1792)=U1
    //              | [1792,2304)=W2 | [2304,2816)=U2
    for (int idx = tid; idx < 2816 * 4; idx += NTHR) {
        int r = idx >> 2, p = idx & 3;
        const float* src; int k;
        if      (r < 256)  { src = W0; k = r; }
        else if (r < 768)  { src = U0; k = r - 256; }
        else if (r < 1280) { src = W1; k = r - 768; }
        else if (r < 1792) { src = U1; k = r - 1280; }
        else if (r < 2304) { src = W2; k = r - 1792; }
        else               { src = U2; k = r - 2304; }
        *(float4*)&w_s[r * 16 + p * 4] =
            *(const float4*)(src + (size_t)k * Gsz + p * Hsz + j0);
    }
    if (tid < 48) {
        int l = tid >> 4, c = tid & 15;
        const float* bl = (l == 0) ? b0 : ((l == 1) ? b1 : b2);
        bias_s[tid] = bl[(c >> 2) * Hsz + j0 + (c & 3)];
    }
    // zero the h slots first read as "h_{-1}": H0[0], H1[1], H2[0]
    if (tid < 256) {
        int o = gb * Hsz + j0 + gj;
        g_H[0][0][o] = 0.0f;
        g_H[1][1][o] = 0.0f;
        g_H[2][0][o] = 0.0f;
    }
    float c0 = 0.0f, c1 = 0.0f, c2 = 0.0f;
    float h0v = 0.0f, h1v = 0.0f, h2v = 0.0f;
    bar_arrive(&s_my);

    // GEMM region: NKQ k-quads from A rows (APR0/APR1 base ptrs, k advances
    // by 4 floats) against w_s rows starting at WB. w loads warp-uniform.
    #define GEMM_REG(APR0, APR1, WB, NKQ, UNR)                                    \
        do {                                                                      \
            const float* a0p_ = (APR0);                                           \
            const float* a1p_ = (APR1);                                           \
            const float* wb_  = w_s + (size_t)(WB) * 16 + cgp * 8;                \
            _Pragma(UNR)                                                          \
            for (int kq = 0; kq < (NKQ); kq++) {                                  \
                float4 a0 = *(const float4*)(a0p_ + kq * 4);                      \
                float4 a1 = *(const float4*)(a1p_ + kq * 4);                      \
                _Pragma("unroll")                                                 \
                for (int j = 0; j < 4; j++) {                                     \
                    const float* wr_ = wb_ + (kq * 4 + j) * 16;                   \
                    ulonglong2 wlo = *(const ulonglong2*)wr_;                     \
                    ulonglong2 whi = *(const ulonglong2*)(wr_ + 4);               \
                    u64 ar0 = rep2(((const float*)&a0)[j]);                       \
                    u64 ar1 = rep2(((const float*)&a1)[j]);                       \
                    fma2(acc[0][0], ar0, wlo.x); fma2(acc[0][1], ar0, wlo.y);     \
                    fma2(acc[0][2], ar0, whi.x); fma2(acc[0][3], ar0, whi.y);     \
                    fma2(acc[1][0], ar1, wlo.x); fma2(acc[1][1], ar1, wlo.y);     \
                    fma2(acc[1][2], ar1, whi.x); fma2(acc[1][3], ar1, whi.y);     \
                }                                                                 \
            }                                                                     \
        } while (0)

    #define ZSTORE()                                                              \
        do {                                                                      \
            _Pragma("unroll")                                                     \
            for (int u = 0; u < 2; u++) {                                         \
                int row_ = u ? r1 : r0;                                           \
                _Pragma("unroll")                                                 \
                for (int p = 0; p < 4; p++)                                       \
                    *(float2*)&zred[ks * 1152 + row_ * 18 + cgp * 8 + p * 2] =    \
                        *(float2*)&acc[u][p];                                     \
            }                                                                     \
        } while (0)

    // gates for layer LI: z from zred+bias, update CR/HV, publish to HDST
    #define GATES(LI, CR, HV, HDST)                                               \
        do {                                                                      \
            float z_[4];                                                          \
            _Pragma("unroll")                                                     \
            for (int g = 0; g < 4; g++) {                                         \
                int c_ = g * 4 + gj;                                              \
                float sum_ = bias_s[(LI) * 16 + c_];                              \
                _Pragma("unroll")                                                 \
                for (int m = 0; m < 8; m++)                                       \
                    sum_ += zred[m * 1152 + gb * 18 + c_];                        \
                z_[g] = sum_;                                                     \
            }                                                                     \
            float ig_ = fsig(z_[0]);                                              \
            float fg_ = fsig(z_[1]);                                              \
            float gg_ = ftanh(z_[2]);                                             \
            float og_ = fsig(z_[3]);                                              \
            CR = fg_ * CR + ig_ * gg_;                                            \
            HV = og_ * ftanh(CR);                                                 \
            (HDST)[gb * Hsz + j0 + gj] = HV;                                      \
        } while (0)

    const size_t S = (size_t)Bsz * Hsz;

    for (int s = 0; s < NSTEP; s++) {
        const int rd = s & 1, wr = rd ^ 1;
        const bool L0 = (s < 512);
        const bool L1 = (s >= 1) && (s <= 512);
        const bool L2 = (s >= 2);
        u64 acc[2][4];

        // ---- pre-wait: layer0 x-part (x0 is barrier-independent) ----
        if (L0) {
            #pragma unroll
            for (int u = 0; u < 2; u++)
                #pragma unroll
                for (int p = 0; p < 4; p++) acc[u][p] = 0ull;
            GEMM_REG(x0 + ((size_t)r0 * Tsz + s) * Dsz + ks * 32,
                     x0 + ((size_t)r1 * Tsz + s) * Dsz + ks * 32,
                     ks * 32, 8, "unroll");
        }

        bar_wait(&s_my);

        // ---- layer 0 h-part + gates ----
        if (L0) {
            const float* h0 = g_H[0][rd];
            GEMM_REG(h0 + r0 * Hsz + ks * 64, h0 + r1 * Hsz + ks * 64,
                     256 + ks * 64, 16, "unroll 8");
        }
        __syncthreads();
        if (L0) ZSTORE();
        __syncthreads();
        if (L0 && tid < 256) {
            GATES(0, c0, h0v, g_H[0][wr]);
            if (s == 511) {
                size_t off = (size_t)gb * Hsz + j0 + gj;
                out[1 * S + off] = h0v;
                out[2 * S + off] = c0;
            }
        }

        // ---- layer 1 (x-input = h0 from prev step = g_H[0][rd]) ----
        if (L1) {
            #pragma unroll
            for (int u = 0; u < 2; u++)
                #pragma unroll
                for (int p = 0; p < 4; p++) acc[u][p] = 0ull;
            const float* x1 = g_H[0][rd];
            const float* h1 = g_H[1][rd];
            GEMM_REG(x1 + r0 * Hsz + ks * 64, x1 + r1 * Hsz + ks * 64,
                     768 + ks * 64, 16, "unroll 8");
            GEMM_REG(h1 + r0 * Hsz + ks * 64, h1 + r1 * Hsz + ks * 64,
                     1280 + ks * 64, 16, "unroll 8");
        }
        __syncthreads();
        if (L1) ZSTORE();
        __syncthreads();
        if (L1 && tid >= 256) {
            GATES(1, c1, h1v, g_H[1][wr]);
            if (s == 512) {
                size_t off = (size_t)gb * Hsz + j0 + gj;
                out[3 * S + off] = h1v;
                out[4 * S + off] = c1;
            }
        }

        // ---- layer 2 (x-input = h1 from prev step = g_H[1][rd]) ----
        if (L2) {
            #pragma unroll
            for (int u = 0; u < 2; u++)
                #pragma unroll
                for (int p = 0; p < 4; p++) acc[u][p] = 0ull;
            const float* x2 = g_H[1][rd];
            const float* h2 = g_H[2][rd];
            GEMM_REG(x2 + r0 * Hsz + ks * 64, x2 + r1 * Hsz + ks * 64,
                     1792 + ks * 64, 16, "unroll 8");
            GEMM_REG(h2 + r0 * Hsz + ks * 64, h2 + r1 * Hsz + ks * 64,
                     2304 + ks * 64, 16, "unroll 8");
        }
        __syncthreads();
        if (L2) ZSTORE();
        __syncthreads();
        if (L2 && tid < 256) {
            GATES(2, c2, h2v, g_H[2][wr]);
            if (s == 513) {
                size_t off = (size_t)gb * Hsz + j0 + gj;
                out[off]         = h2v;
                out[5 * S + off] = h2v;
                out[6 * S + off] = c2;
            }
        }

        bar_arrive(&s_my);
    }
    #undef GEMM_REG
    #undef ZSTORE
    #undef GATES
}

extern "C" void kernel_launch(void* const* d_in, const int* in_sizes, int n_in,
                              void* d_out, int out_size) {
    (void)in_sizes; (void)n_in; (void)out_size;
    static int attr_done = 0;
    if (!attr_done) {
        cudaFuncSetAttribute(lstm_kernel,
                             cudaFuncAttributeMaxDynamicSharedMemorySize, SMEM_BYTES);
        attr_done = 1;
    }
    lstm_kernel<<<NBLK, NTHR, SMEM_BYTES>>>(
        (const float*)d_in[0],
        (const float*)d_in[1], (const float*)d_in[2], (const float*)d_in[3],
        (const float*)d_in[4], (const float*)d_in[5], (const float*)d_in[6],
        (const float*)d_in[7], (const float*)d_in[8], (const float*)d_in[9],
        (float*)d_out);
}

// round 17
// speedup vs baseline: 2.1257x; 2.1257x over previous
#include <cuda_runtime.h>

// Stacked LSTM: B=64, T=512, D=256, H=512, 3 layers. fp32.
// R17: R13 skeleton (persistent, 128 blocks x 512 threads, split-phase
// single-counter grid barrier, weights resident in smem, x-part pre-wait)
// with WARP-AUTONOMOUS GEMM: warp (ks<8, rh<2) owns a 32-row x 32-k tile per
// 256-k sweep. It LDGs its tile coalesced (4 lines/LDG), STS into a private
// XOR-swizzled 4KB smem region, __syncwarp, computes (w broadcast from w_s,
// acc across sweeps). NO __syncthreads in the GEMM; 2 per step total.

#define Bsz 64
#define Tsz 512
#define Dsz 256
#define Hsz 512
#define Gsz 2048
#define NBLK 128
#define NTHR 512

typedef unsigned long long u64;

// smem floats: w_s [1024][16] 16384 | a_s [16 warps][1024] 16384 |
//              zred [8][64][18] 9216 | bias 16
#define SM_WS   0
#define SM_AS   16384
#define SM_ZR   (16384 + 16384)
#define SM_BIAS (16384 + 16384 + 9216)
#define SMEM_FLOATS (SM_BIAS + 16)
#define SMEM_BYTES (SMEM_FLOATS * 4)   // 168,064 B

// swizzled offset within a warp's 32x32 tile (k4 = float offset, mult of 4)
#define SWZ(row, k4) ((row) * 32 + ((k4) ^ (((row) & 7) << 2)))

__device__ float g_seqA[(size_t)Bsz * Tsz * Hsz];
__device__ float g_seqB[(size_t)Bsz * Tsz * Hsz];
__device__ float g_hbuf[2][Bsz * Hsz];
__device__ unsigned g_count = 0;
__device__ unsigned g_gen = 0;

__device__ __forceinline__ void bar_arrive(unsigned* s_my) {
    __syncthreads();
    if (threadIdx.x == 0) {
        unsigned my;
        asm volatile("ld.relaxed.gpu.u32 %0, [%1];" : "=r"(my) : "l"(&g_gen));
        *s_my = my;
        __threadfence();
        unsigned old = atomicAdd(&g_count, 1u);
        if (old == NBLK - 1) {
            g_count = 0;
            __threadfence();
            asm volatile("st.release.gpu.u32 [%0], %1;" :: "l"(&g_gen), "r"(my + 1u));
        }
    }
}
__device__ __forceinline__ void bar_wait(unsigned* s_my) {
    if (threadIdx.x == 0) {
        unsigned my = *s_my, g;
        do {
            asm volatile("ld.acquire.gpu.u32 %0, [%1];" : "=r"(g) : "l"(&g_gen));
        } while (g == my);
    }
    __syncthreads();
}

__device__ __forceinline__ float fsig(float x) {
    return __fdividef(1.0f, 1.0f + __expf(-x));
}
__device__ __forceinline__ float ftanh(float x) {
    float e = __expf(2.0f * x);
    return 1.0f - __fdividef(2.0f, e + 1.0f);
}
__device__ __forceinline__ void fma2(u64& d, u64 a, u64 b) {
    asm("fma.rn.f32x2 %0, %1, %2, %0;" : "+l"(d) : "l"(a), "l"(b));
}
__device__ __forceinline__ u64 rep2(float x) {
    u64 r;
    asm("mov.b64 %0, {%1, %1};" : "=l"(r) : "f"(x));
    return r;
}

extern "C" __global__ void __launch_bounds__(NTHR, 1)
lstm_kernel(const float* __restrict__ x0,
            const float* __restrict__ W0, const float* __restrict__ U0, const float* __restrict__ b0,
            const float* __restrict__ W1, const float* __restrict__ U1, const float* __restrict__ b1,
            const float* __restrict__ W2, const float* __restrict__ U2, const float* __restrict__ b2,
            float* __restrict__ out)
{
    extern __shared__ float smem[];
    float* w_s    = smem + SM_WS;     // [k][16]
    float* zred   = smem + SM_ZR;     // [8][64][18]
    float* bias_s = smem + SM_BIAS;   // [16]
    float* zpart  = smem + SM_AS;     // gather scratch [4][256] (a_s idle then)
    __shared__ unsigned s_my;

    const int tid  = threadIdx.x;
    const int bc   = blockIdx.x;
    const int j0   = bc * 4;
    const int wid  = tid >> 5;
    const int ks   = wid & 7;          // k-split group: k [ks*32, ks*32+32) per sweep
    const int rh   = wid >> 3;         // row half: rows [rh*32, rh*32+32)
    const int lane = tid & 31;
    const int rbase = rh * 32;
    // staging lanes: kl spans 128B of k, rl spans rows (4 lines/LDG)
    const int kl = lane & 7;           // k float4 idx 0..7
    const int rl = lane >> 3;          // 0..3 : rows rl + 4*rep
    // compute lanes
    const int rg = lane & 15;          // local rows rg, rg+16
    const int ch = lane >> 4;          // col half: cols ch*8..+8
    // gate mapping
    const int gb = (tid & 255) >> 2;
    const int gj = tid & 3;

    float* aw = smem + SM_AS + wid * 1024;   // warp-private 32x32 tile

    for (int layer = 0; layer < 3; layer++) {
        const float* Wl = (layer == 0) ? W0 : ((layer == 1) ? W1 : W2);
        const float* Ul = (layer == 0) ? U0 : ((layer == 1) ? U1 : U2);
        const float* bl = (layer == 0) ? b0 : ((layer == 1) ? b1 : b2);
        const float* xsrc = (layer == 0) ? x0 : ((layer == 1) ? g_seqA : g_seqB);
        float* seqout = (layer == 0) ? g_seqA : ((layer == 1) ? g_seqB : (float*)0);
        const int K_in = (layer == 0) ? Dsz : Hsz;
        const int Ktot = K_in + Hsz;        // 768 or 1024
        const int nsw  = Ktot >> 8;         // sweeps: 3 or 4
        const int nx   = K_in >> 8;         // x sweeps: 1 or 2

        // ---- weights resident in smem (once per layer) ----
        for (int idx = tid; idx < Ktot * 4; idx += NTHR) {
            int gk = idx >> 2, p = idx & 3;
            const float* wrow = (gk < K_in) ? (Wl + (size_t)gk * Gsz)
                                            : (Ul + (size_t)(gk - K_in) * Gsz);
            *(float4*)&w_s[gk * 16 + p * 4] = *(const float4*)(wrow + p * Hsz + j0);
        }
        if (tid < 16) bias_s[tid] = bl[(tid >> 2) * Hsz + j0 + (tid & 3)];
        float c_reg = 0.0f, hval = 0.0f;
        if (tid < 256) g_hbuf[0][gb * Hsz + j0 + gj] = 0.0f;
        int cur = 0;
        bar_arrive(&s_my);   // publish zeroed h_0; also fences w_s reload order

        float4 st[8];
        // LDG this warp's 32x32 tile of sweep S at step TT (4 lines per LDG)
        #define LDG_TILE(TT, S)                                                       \
            do {                                                                      \
                int kb_ = (S) * 256 + ks * 32 + kl * 4;                               \
                if (kb_ < K_in) {                                                     \
                    _Pragma("unroll")                                                 \
                    for (int r_ = 0; r_ < 8; r_++)                                    \
                        st[r_] = *(const float4*)(xsrc +                              \
                            ((size_t)(rbase + rl + 4 * r_) * Tsz + (TT)) * K_in + kb_); \
                } else {                                                              \
                    const float* s_ = hsrc + (kb_ - K_in);                            \
                    _Pragma("unroll")                                                 \
                    for (int r_ = 0; r_ < 8; r_++)                                    \
                        st[r_] = *(const float4*)(s_ + (rbase + rl + 4 * r_) * Hsz);  \
                }                                                                     \
            } while (0)

        #define STS_TILE()                                                            \
            do {                                                                      \
                _Pragma("unroll")                                                     \
                for (int r_ = 0; r_ < 8; r_++) {                                      \
                    int row_ = rl + 4 * r_;                                           \
                    *(float4*)&aw[SWZ(row_, kl * 4)] = st[r_];                        \
                }                                                                     \
            } while (0)

        // compute this warp's sweep-S slice; w loads warp-uniform (broadcast)
        #define COMPUTE_SWEEP(S)                                                      \
            do {                                                                      \
                const float* wb = w_s + ((S) * 256 + ks * 32) * 16 + ch * 8;          \
                _Pragma("unroll")                                                     \
                for (int kq = 0; kq < 8; kq++) {                                      \
                    float4 a0 = *(const float4*)&aw[SWZ(rg, kq * 4)];                 \
                    float4 a1 = *(const float4*)&aw[SWZ(rg + 16, kq * 4)];            \
                    _Pragma("unroll")                                                 \
                    for (int j = 0; j < 4; j++) {                                     \
                        const float* wr = wb + (kq * 4 + j) * 16;                     \
                        ulonglong2 wlo = *(const ulonglong2*)wr;                      \
                        ulonglong2 whi = *(const ulonglong2*)(wr + 4);                \
                        u64 ar0 = rep2(((const float*)&a0)[j]);                       \
                        u64 ar1 = rep2(((const float*)&a1)[j]);                       \
                        fma2(acc[0][0], ar0, wlo.x); fma2(acc[0][1], ar0, wlo.y);     \
                        fma2(acc[0][2], ar0, whi.x); fma2(acc[0][3], ar0, whi.y);     \
                        fma2(acc[1][0], ar1, wlo.x); fma2(acc[1][1], ar1, wlo.y);     \
                        fma2(acc[1][2], ar1, whi.x); fma2(acc[1][3], ar1, whi.y);     \
                    }                                                                 \
                }                                                                     \
            } while (0)

        {
            const float* hsrc = g_hbuf[0];
            LDG_TILE(0, 0);   // step-0 x sweep (barrier-independent)
            (void)hsrc;
        }

        for (int t = 0; t < Tsz; t++) {
            const float* hsrc = g_hbuf[cur];
            u64 acc[2][4] = {};

            // ---- x sweeps (pre-wait; warp-autonomous, no block syncs) ----
            for (int s = 0; s < nx; s++) {
                __syncwarp();
                STS_TILE();
                if (s + 1 < nx) LDG_TILE(t, s + 1);
                __syncwarp();
                COMPUTE_SWEEP(s);
            }

            // ---- wait for h_t, then h sweeps ----
            bar_wait(&s_my);
            LDG_TILE(t, nx);
            for (int s = nx; s < nsw; s++) {
                __syncwarp();
                STS_TILE();
                if (s + 1 < nsw) LDG_TILE(t, s + 1);
                __syncwarp();
                COMPUTE_SWEEP(s);
            }

            // ---- k-split partials (warp-private slice of zred) ----
            #pragma unroll
            for (int u = 0; u < 2; u++) {
                int row = rbase + rg + 16 * u;
                #pragma unroll
                for (int p = 0; p < 4; p++)
                    *(float2*)&zred[ks * 1152 + row * 18 + ch * 8 + p * 2] =
                        *(float2*)&acc[u][p];
            }
            __syncthreads();

            // ---- split gather: upper half pre-sums k-groups 4..7 ----
            if (tid >= 256) {
                #pragma unroll
                for (int g = 0; g < 4; g++) {
                    int o = gb * 18 + g * 4 + gj;
                    float s = zred[4 * 1152 + o] + zred[5 * 1152 + o]
                            + zred[6 * 1152 + o] + zred[7 * 1152 + o];
                    zpart[g * 256 + (tid - 256)] = s;
                }
            }
            __syncthreads();

            // ---- gates (tid < 256: one thread per (b, j)) ----
            if (tid < 256) {
                float z[4];
                #pragma unroll
                for (int g = 0; g < 4; g++) {
                    int o = gb * 18 + g * 4 + gj;
                    z[g] = bias_s[g * 4 + gj] + zpart[g * 256 + tid]
                         + zred[o] + zred[1152 + o] + zred[2304 + o] + zred[3456 + o];
                }
                float ig = fsig(z[0]);
                float fg = fsig(z[1]);
                float gg = ftanh(z[2]);
                float og = fsig(z[3]);
                c_reg = fg * c_reg + ig * gg;
                hval  = og * ftanh(c_reg);
                g_hbuf[cur ^ 1][gb * Hsz + j0 + gj] = hval;
                if (seqout)
                    seqout[((size_t)(gb * Tsz + t)) * Hsz + j0 + gj] = hval;
            }
            cur ^= 1;

            if (t + 1 < Tsz) LDG_TILE(t + 1, 0);  // prefetch next x tile
            bar_arrive(&s_my);                     // publish h_{t+1} (+seq row)
        }
        bar_wait(&s_my);   // layer complete everywhere

        // ---- layer finals. Output: [out(=h2) | h0 | c0 | h1 | c1 | h2 | c2] ----
        if (tid < 256) {
            size_t off = (size_t)gb * Hsz + j0 + gj;
            const size_t S = (size_t)Bsz * Hsz;
            if (layer == 0)      { out[1 * S + off] = hval; out[2 * S + off] = c_reg; }
            else if (layer == 1) { out[3 * S + off] = hval; out[4 * S + off] = c_reg; }
            else                 { out[off] = hval; out[5 * S + off] = hval; out[6 * S + off] = c_reg; }
        }
        #undef LDG_TILE
        #undef STS_TILE
        #undef COMPUTE_SWEEP
    }
}

extern "C" void kernel_launch(void* const* d_in, const int* in_sizes, int n_in,
                              void* d_out, int out_size) {
    (void)in_sizes; (void)n_in; (void)out_size;
    static int attr_done = 0;
    if (!attr_done) {
        cudaFuncSetAttribute(lstm_kernel,
                             cudaFuncAttributeMaxDynamicSharedMemorySize, SMEM_BYTES);
        attr_done = 1;
    }
    lstm_kernel<<<NBLK, NTHR, SMEM_BYTES>>>(
        (const float*)d_in[0],
        (const float*)d_in[1], (const float*)d_in[2], (const float*)d_in[3],
        (const float*)d_in[4], (const float*)d_in[5], (const float*)d_in[6],
        (const float*)d_in[7], (const float*)d_in[8], (const float*)d_in[9],
        (float*)d_out);
}